// round 1
// baseline (speedup 1.0000x reference)
#include <cuda_runtime.h>

#define NNODES 50000
#define EDGES  800000
#define DHID   128
#define RREL   8
#define KACC   (RREL * DHID)   /* 1024 */
#define KTOT   (KACC + DHID)   /* 1152 */

#define BM 64
#define BK 16

// Scratch (device globals — no allocation allowed in kernel_launch)
__device__ float g_acc[(size_t)NNODES * KACC];   // 204.8 MB, [N][R*128]
__device__ float g_h[(size_t)NNODES * DHID];     // 25.6 MB, layer-1 output

// ---------------------------------------------------------------------------
// Zero the accumulator (float4 stores, write-bound)
// ---------------------------------------------------------------------------
__global__ void zero_acc_kernel() {
    size_t i = (size_t)blockIdx.x * blockDim.x + threadIdx.x;
    size_t n4 = (size_t)NNODES * KACC / 4;
    if (i < n4) {
        reinterpret_cast<float4*>(g_acc)[i] = make_float4(0.f, 0.f, 0.f, 0.f);
    }
}

// ---------------------------------------------------------------------------
// Edge scatter: acc[dst][et*128 + :] += x[src][:]
// One warp per edge, each lane handles one float4 (32 lanes * 4 = 128).
// Vector atomics: red.global.add.v4.f32 (sm_90+)
// ---------------------------------------------------------------------------
__global__ void scatter_kernel(const float* __restrict__ xsrc, int use_h,
                               const int* __restrict__ src,
                               const int* __restrict__ dst,
                               const int* __restrict__ et) {
    int warp = (blockIdx.x * blockDim.x + threadIdx.x) >> 5;
    if (warp >= EDGES) return;
    int lane = threadIdx.x & 31;

    const float* xp = use_h ? g_h : xsrc;
    int s = src[warp];
    int d = dst[warp];
    int r = et[warp];

    float4 v = reinterpret_cast<const float4*>(xp + (size_t)s * DHID)[lane];
    float* p = g_acc + (size_t)d * KACC + r * DHID + lane * 4;
    asm volatile("red.global.add.v4.f32 [%0], {%1,%2,%3,%4};"
                 :: "l"(p), "f"(v.x), "f"(v.y), "f"(v.z), "f"(v.w)
                 : "memory");
}

// ---------------------------------------------------------------------------
// Fused GEMM: out[n][o] = epi( sum_k A[n][k] * Bstack[k][o] + bias[o] )
//   A[n][0:1024]   = g_acc row n        (aggregated messages)
//   A[n][1024:1152]= xin row n          (self-loop input)
//   Bstack[0:1024] = Wrel (= W[r][i][o] flattened as [(r*128+i)][o])
//   Bstack[1024:]  = Wloop
// Tile: 64 rows x 128 cols (full width), BK=16, 256 threads,
// per-thread micro-tile 8x4. Epilogue: ReLU (layer 1) or L2-normalize (layer 2).
// ---------------------------------------------------------------------------
__global__ void gemm_kernel(const float* __restrict__ xin, int xin_is_h,
                            const float* __restrict__ Wrel,   // [1024][128]
                            const float* __restrict__ Wloop,  // [128][128]
                            const float* __restrict__ bias,   // [128]
                            float* __restrict__ out, int out_is_h,
                            int do_norm) {
    __shared__ float As[BK][BM];        // transposed: As[k][m]
    __shared__ float Bs[BK][DHID];
    __shared__ float rowsq[BM];

    const float* xp = xin_is_h ? g_h : xin;
    float*       op = out_is_h ? g_h : out;

    int tid = threadIdx.x;
    int tx  = tid & 31;          // col group: cols tx*4 .. tx*4+3
    int ty  = tid >> 5;          // 0..7: rows ty*8 .. ty*8+7
    int row0 = blockIdx.x * BM;

    float acc[8][4];
#pragma unroll
    for (int i = 0; i < 8; i++)
#pragma unroll
        for (int j = 0; j < 4; j++) acc[i][j] = 0.f;

    int lm = tid & 63;           // A-load: row within tile
    int kq = tid >> 6;           // A-load: which float4 of the 16-wide k slab

#pragma unroll 1
    for (int t = 0; t < KTOT / BK; ++t) {
        int k0 = t * BK;

        // --- load A tile (transpose into As[k][m]) ---
        {
            int gr = row0 + lm;
            float4 a;
            if (gr < NNODES) {
                if (k0 < KACC) {
                    a = *reinterpret_cast<const float4*>(
                        g_acc + (size_t)gr * KACC + k0 + kq * 4);
                } else {
                    a = *reinterpret_cast<const float4*>(
                        xp + (size_t)gr * DHID + (k0 - KACC) + kq * 4);
                }
            } else {
                a = make_float4(0.f, 0.f, 0.f, 0.f);
            }
            As[kq * 4 + 0][lm] = a.x;
            As[kq * 4 + 1][lm] = a.y;
            As[kq * 4 + 2][lm] = a.z;
            As[kq * 4 + 3][lm] = a.w;
        }
        // --- load B tile (2 float4 per thread, fully coalesced) ---
        {
#pragma unroll
            for (int u = 0; u < 2; ++u) {
                int e  = tid + u * 256;   // 0..511
                int kk = e >> 5;          // 0..15
                int c4 = e & 31;          // 0..31
                int gk = k0 + kk;
                const float* bsrc = (gk < KACC)
                    ? (Wrel + (size_t)gk * DHID)
                    : (Wloop + (size_t)(gk - KACC) * DHID);
                *reinterpret_cast<float4*>(&Bs[kk][c4 * 4]) =
                    *reinterpret_cast<const float4*>(bsrc + c4 * 4);
            }
        }
        __syncthreads();

#pragma unroll
        for (int k = 0; k < BK; k++) {
            float4 a0 = *reinterpret_cast<const float4*>(&As[k][ty * 8]);
            float4 a1 = *reinterpret_cast<const float4*>(&As[k][ty * 8 + 4]);
            float4 b  = *reinterpret_cast<const float4*>(&Bs[k][tx * 4]);
            float av[8] = {a0.x, a0.y, a0.z, a0.w, a1.x, a1.y, a1.z, a1.w};
#pragma unroll
            for (int i = 0; i < 8; i++) {
                acc[i][0] += av[i] * b.x;
                acc[i][1] += av[i] * b.y;
                acc[i][2] += av[i] * b.z;
                acc[i][3] += av[i] * b.w;
            }
        }
        __syncthreads();
    }

    // --- epilogue: bias, then ReLU or row L2-normalize ---
    float bj[4];
#pragma unroll
    for (int j = 0; j < 4; j++) bj[j] = bias[tx * 4 + j];
#pragma unroll
    for (int i = 0; i < 8; i++)
#pragma unroll
        for (int j = 0; j < 4; j++) acc[i][j] += bj[j];

    if (!do_norm) {
#pragma unroll
        for (int i = 0; i < 8; i++) {
            int gr = row0 + ty * 8 + i;
            if (gr < NNODES) {
                float4 v = make_float4(fmaxf(acc[i][0], 0.f),
                                       fmaxf(acc[i][1], 0.f),
                                       fmaxf(acc[i][2], 0.f),
                                       fmaxf(acc[i][3], 0.f));
                *reinterpret_cast<float4*>(op + (size_t)gr * DHID + tx * 4) = v;
            }
        }
    } else {
        if (tid < BM) rowsq[tid] = 0.f;
        __syncthreads();
#pragma unroll
        for (int i = 0; i < 8; i++) {
            float s = acc[i][0] * acc[i][0] + acc[i][1] * acc[i][1]
                    + acc[i][2] * acc[i][2] + acc[i][3] * acc[i][3];
            atomicAdd(&rowsq[ty * 8 + i], s);
        }
        __syncthreads();
#pragma unroll
        for (int i = 0; i < 8; i++) {
            int gr = row0 + ty * 8 + i;
            if (gr < NNODES) {
                float nrm = sqrtf(rowsq[ty * 8 + i]);
                float inv = 1.0f / fmaxf(nrm, 1e-12f);
                float4 v = make_float4(acc[i][0] * inv, acc[i][1] * inv,
                                       acc[i][2] * inv, acc[i][3] * inv);
                *reinterpret_cast<float4*>(op + (size_t)gr * DHID + tx * 4) = v;
            }
        }
    }
}

// ---------------------------------------------------------------------------
// Launch: zero -> scatter(x) -> gemm1(relu->g_h) -> zero -> scatter(g_h)
//         -> gemm2(normalize->out)
// ---------------------------------------------------------------------------
extern "C" void kernel_launch(void* const* d_in, const int* in_sizes, int n_in,
                              void* d_out, int out_size) {
    const float* x      = (const float*)d_in[0];
    const float* W1     = (const float*)d_in[1];
    const float* loopW1 = (const float*)d_in[2];
    const float* b1     = (const float*)d_in[3];
    const float* W2     = (const float*)d_in[4];
    const float* loopW2 = (const float*)d_in[5];
    const float* b2     = (const float*)d_in[6];
    const int*   src    = (const int*)d_in[7];
    const int*   dst    = (const int*)d_in[8];
    const int*   et     = (const int*)d_in[9];
    float* out = (float*)d_out;

    int zblocks = (int)(((size_t)NNODES * KACC / 4 + 255) / 256);  // 50000
    int sblocks = (int)(((size_t)EDGES * 32 + 255) / 256);         // 100000
    int gblocks = (NNODES + BM - 1) / BM;                          // 782

    // Layer 1
    zero_acc_kernel<<<zblocks, 256>>>();
    scatter_kernel<<<sblocks, 256>>>(x, 0, src, dst, et);
    gemm_kernel<<<gblocks, 256>>>(x, 0, W1, loopW1, b1, nullptr, 1, 0);

    // Layer 2
    zero_acc_kernel<<<zblocks, 256>>>();
    scatter_kernel<<<sblocks, 256>>>(nullptr, 1, src, dst, et);
    gemm_kernel<<<gblocks, 256>>>(nullptr, 1, W2, loopW2, b2, out, 0, 1);
}

// round 2
// speedup vs baseline: 1.0185x; 1.0185x over previous
#include <cuda_runtime.h>

#define NNODES 50000
#define EDGES  800000
#define DHID   128
#define RREL   8
#define KACC   (RREL * DHID)   /* 1024 */
#define KTOT   (KACC + DHID)   /* 1152 */

#define BM 64
#define BK 16

// Scratch (device globals — no allocation allowed in kernel_launch)
__device__ float g_acc[(size_t)NNODES * KACC];   // 204.8 MB, [N][R*128]
__device__ float g_h[(size_t)NNODES * DHID];     // 25.6 MB, layer-1 output

// ---------------------------------------------------------------------------
// Packed f32x2 helpers (Blackwell FFMA2 — only reachable via PTX)
// ---------------------------------------------------------------------------
__device__ __forceinline__ unsigned long long dup_f32x2(float x) {
    unsigned long long r;
    asm("mov.b64 %0, {%1, %1};" : "=l"(r) : "f"(x));
    return r;
}
__device__ __forceinline__ void fma_f32x2(unsigned long long& d,
                                          unsigned long long a,
                                          unsigned long long b) {
    asm("fma.rn.f32x2 %0, %1, %2, %0;" : "+l"(d) : "l"(a), "l"(b));
}
__device__ __forceinline__ void unpack_f32x2(unsigned long long v,
                                             float& lo, float& hi) {
    asm("mov.b64 {%0, %1}, %2;" : "=f"(lo), "=f"(hi) : "l"(v));
}

// ---------------------------------------------------------------------------
// Zero the accumulator (float4 stores, write-bound)
// ---------------------------------------------------------------------------
__global__ void zero_acc_kernel() {
    size_t i = (size_t)blockIdx.x * blockDim.x + threadIdx.x;
    size_t n4 = (size_t)NNODES * KACC / 4;
    if (i < n4) {
        reinterpret_cast<float4*>(g_acc)[i] = make_float4(0.f, 0.f, 0.f, 0.f);
    }
}

// ---------------------------------------------------------------------------
// Edge scatter: acc[dst][et*128 + :] += x[src][:]
// One warp per edge; red.global.add.v4.f32
// ---------------------------------------------------------------------------
__global__ void scatter_kernel(const float* __restrict__ xsrc, int use_h,
                               const int* __restrict__ src,
                               const int* __restrict__ dst,
                               const int* __restrict__ et) {
    int warp = (blockIdx.x * blockDim.x + threadIdx.x) >> 5;
    if (warp >= EDGES) return;
    int lane = threadIdx.x & 31;

    const float* xp = use_h ? g_h : xsrc;
    int s = src[warp];
    int d = dst[warp];
    int r = et[warp];

    float4 v = reinterpret_cast<const float4*>(xp + (size_t)s * DHID)[lane];
    float* p = g_acc + (size_t)d * KACC + r * DHID + lane * 4;
    asm volatile("red.global.add.v4.f32 [%0], {%1,%2,%3,%4};"
                 :: "l"(p), "f"(v.x), "f"(v.y), "f"(v.z), "f"(v.w)
                 : "memory");
}

// ---------------------------------------------------------------------------
// Fused GEMM with packed FFMA2 inner loop.
//   out[n][o] = epi( sum_k A[n][k] * Bstack[k][o] + bias[o] )
// Tile: 64 rows x 128 cols, BK=16, 256 threads.
// Per-thread micro-tile: 8 rows x 4 cols, stored as acc2[4 row-pairs][4 cols]
// in packed f32x2 registers.
// ---------------------------------------------------------------------------
__global__ void gemm_kernel(const float* __restrict__ xin, int xin_is_h,
                            const float* __restrict__ Wrel,   // [1024][128]
                            const float* __restrict__ Wloop,  // [128][128]
                            const float* __restrict__ bias,   // [128]
                            float* __restrict__ out, int out_is_h,
                            int do_norm) {
    __shared__ float As[BK][BM];        // transposed: As[k][m]
    __shared__ float Bs[BK][DHID];
    __shared__ float rowsq[BM];

    const float* xp = xin_is_h ? g_h : xin;
    float*       op = out_is_h ? g_h : out;

    int tid = threadIdx.x;
    int tx  = tid & 31;          // cols tx*4 .. tx*4+3
    int ty  = tid >> 5;          // rows ty*8 .. ty*8+7
    int row0 = blockIdx.x * BM;

    // acc2[p][j]: packed (row 2p, row 2p+1) x col j
    unsigned long long acc2[4][4];
#pragma unroll
    for (int p = 0; p < 4; p++)
#pragma unroll
        for (int j = 0; j < 4; j++) acc2[p][j] = 0ull;

    int lm = tid & 63;           // A-load: row within tile
    int kq = tid >> 6;           // A-load: float4 index within k-slab

#pragma unroll 1
    for (int t = 0; t < KTOT / BK; ++t) {
        int k0 = t * BK;

        // --- load A tile (transpose into As[k][m]) ---
        {
            int gr = row0 + lm;
            float4 a;
            if (gr < NNODES) {
                if (k0 < KACC) {
                    a = *reinterpret_cast<const float4*>(
                        g_acc + (size_t)gr * KACC + k0 + kq * 4);
                } else {
                    a = *reinterpret_cast<const float4*>(
                        xp + (size_t)gr * DHID + (k0 - KACC) + kq * 4);
                }
            } else {
                a = make_float4(0.f, 0.f, 0.f, 0.f);
            }
            As[kq * 4 + 0][lm] = a.x;
            As[kq * 4 + 1][lm] = a.y;
            As[kq * 4 + 2][lm] = a.z;
            As[kq * 4 + 3][lm] = a.w;
        }
        // --- load B tile (2 float4 per thread, coalesced) ---
        {
#pragma unroll
            for (int u = 0; u < 2; ++u) {
                int e  = tid + u * 256;   // 0..511
                int kk = e >> 5;          // 0..15
                int c4 = e & 31;          // 0..31
                int gk = k0 + kk;
                const float* bsrc = (gk < KACC)
                    ? (Wrel + (size_t)gk * DHID)
                    : (Wloop + (size_t)(gk - KACC) * DHID);
                *reinterpret_cast<float4*>(&Bs[kk][c4 * 4]) =
                    *reinterpret_cast<const float4*>(bsrc + c4 * 4);
            }
        }
        __syncthreads();

#pragma unroll
        for (int k = 0; k < BK; k++) {
            // Row-pairs arrive pre-packed from the LDS.128:
            ulonglong2 ap01 = *reinterpret_cast<const ulonglong2*>(&As[k][ty * 8]);
            ulonglong2 ap23 = *reinterpret_cast<const ulonglong2*>(&As[k][ty * 8 + 4]);
            float4 b = *reinterpret_cast<const float4*>(&Bs[k][tx * 4]);
            unsigned long long bd[4] = {dup_f32x2(b.x), dup_f32x2(b.y),
                                        dup_f32x2(b.z), dup_f32x2(b.w)};
            unsigned long long ap[4] = {ap01.x, ap01.y, ap23.x, ap23.y};
#pragma unroll
            for (int p = 0; p < 4; p++) {
                fma_f32x2(acc2[p][0], ap[p], bd[0]);
                fma_f32x2(acc2[p][1], ap[p], bd[1]);
                fma_f32x2(acc2[p][2], ap[p], bd[2]);
                fma_f32x2(acc2[p][3], ap[p], bd[3]);
            }
        }
        __syncthreads();
    }

    // --- unpack to scalar 8x4 ---
    float acc[8][4];
#pragma unroll
    for (int p = 0; p < 4; p++)
#pragma unroll
        for (int j = 0; j < 4; j++)
            unpack_f32x2(acc2[p][j], acc[2 * p][j], acc[2 * p + 1][j]);

    // --- epilogue: bias, then ReLU or row L2-normalize ---
    float bj[4];
#pragma unroll
    for (int j = 0; j < 4; j++) bj[j] = bias[tx * 4 + j];
#pragma unroll
    for (int i = 0; i < 8; i++)
#pragma unroll
        for (int j = 0; j < 4; j++) acc[i][j] += bj[j];

    if (!do_norm) {
#pragma unroll
        for (int i = 0; i < 8; i++) {
            int gr = row0 + ty * 8 + i;
            if (gr < NNODES) {
                float4 v = make_float4(fmaxf(acc[i][0], 0.f),
                                       fmaxf(acc[i][1], 0.f),
                                       fmaxf(acc[i][2], 0.f),
                                       fmaxf(acc[i][3], 0.f));
                *reinterpret_cast<float4*>(op + (size_t)gr * DHID + tx * 4) = v;
            }
        }
    } else {
        if (tid < BM) rowsq[tid] = 0.f;
        __syncthreads();
#pragma unroll
        for (int i = 0; i < 8; i++) {
            float s = acc[i][0] * acc[i][0] + acc[i][1] * acc[i][1]
                    + acc[i][2] * acc[i][2] + acc[i][3] * acc[i][3];
            atomicAdd(&rowsq[ty * 8 + i], s);
        }
        __syncthreads();
#pragma unroll
        for (int i = 0; i < 8; i++) {
            int gr = row0 + ty * 8 + i;
            if (gr < NNODES) {
                float nrm = sqrtf(rowsq[ty * 8 + i]);
                float inv = 1.0f / fmaxf(nrm, 1e-12f);
                float4 v = make_float4(acc[i][0] * inv, acc[i][1] * inv,
                                       acc[i][2] * inv, acc[i][3] * inv);
                *reinterpret_cast<float4*>(op + (size_t)gr * DHID + tx * 4) = v;
            }
        }
    }
}

// ---------------------------------------------------------------------------
// Launch: zero -> scatter(x) -> gemm1(relu->g_h) -> zero -> scatter(g_h)
//         -> gemm2(normalize->out)
// ---------------------------------------------------------------------------
extern "C" void kernel_launch(void* const* d_in, const int* in_sizes, int n_in,
                              void* d_out, int out_size) {
    const float* x      = (const float*)d_in[0];
    const float* W1     = (const float*)d_in[1];
    const float* loopW1 = (const float*)d_in[2];
    const float* b1     = (const float*)d_in[3];
    const float* W2     = (const float*)d_in[4];
    const float* loopW2 = (const float*)d_in[5];
    const float* b2     = (const float*)d_in[6];
    const int*   src    = (const int*)d_in[7];
    const int*   dst    = (const int*)d_in[8];
    const int*   et     = (const int*)d_in[9];
    float* out = (float*)d_out;

    int zblocks = (int)(((size_t)NNODES * KACC / 4 + 255) / 256);  // 50000
    int sblocks = (int)(((size_t)EDGES * 32 + 255) / 256);         // 100000
    int gblocks = (NNODES + BM - 1) / BM;                          // 782

    // Layer 1
    zero_acc_kernel<<<zblocks, 256>>>();
    scatter_kernel<<<sblocks, 256>>>(x, 0, src, dst, et);
    gemm_kernel<<<gblocks, 256>>>(x, 0, W1, loopW1, b1, nullptr, 1, 0);

    // Layer 2
    zero_acc_kernel<<<zblocks, 256>>>();
    scatter_kernel<<<sblocks, 256>>>(nullptr, 1, src, dst, et);
    gemm_kernel<<<gblocks, 256>>>(nullptr, 1, W2, loopW2, b2, out, 0, 1);
}

// round 4
// speedup vs baseline: 1.5551x; 1.5268x over previous
#include <cuda_runtime.h>
#include <cuda_bf16.h>
#include <cstdint>

#define NNODES 50000
#define EDGES  800000
#define DHID   128
#define RREL   8
#define KACC   (RREL * DHID)   /* 1024 */
#define KTOT   (KACC + DHID)   /* 1152 */

#define BM   128               /* CTA tile rows */
#define KC   64                /* K chunk       */
#define NCH  (KTOT / KC)       /* 18            */
#define LDSB 72                /* padded row length in bf16 elements (144 B) */
#define TILE_BYTES (128 * LDSB * 2)        /* 18432 per buffer */
#define SMEM_BYTES (4 * TILE_BYTES)        /* Ah, Al, Bh, Bl = 73728 */

// ---------------------------------------------------------------------------
// Scratch (device globals — no allocation allowed)
// ---------------------------------------------------------------------------
__device__ float g_acc[(size_t)NNODES * KACC];            // 204.8 MB
__device__ float g_h[(size_t)NNODES * DHID];              // 25.6 MB
__device__ __nv_bfloat16 g_Bth[2][(size_t)DHID * KTOT];   // B^T hi  [layer][n*1152+k]
__device__ __nv_bfloat16 g_Btl[2][(size_t)DHID * KTOT];   // B^T lo

// ---------------------------------------------------------------------------
// PTX helpers (all standard sm_80-level PTX — no "a" features)
// ---------------------------------------------------------------------------
__device__ __forceinline__ uint32_t smem_u32(const void* p) {
    uint32_t a;
    asm("{ .reg .u64 t; cvta.to.shared.u64 t, %1; cvt.u32.u64 %0, t; }"
        : "=r"(a) : "l"(p));
    return a;
}
__device__ __forceinline__ void sts128(uint32_t a, uint4 v) {
    asm volatile("st.shared.v4.b32 [%0], {%1,%2,%3,%4};"
                 :: "r"(a), "r"(v.x), "r"(v.y), "r"(v.z), "r"(v.w) : "memory");
}
// pack (x1,x0) -> bf16x2 (x0 low), plus bf16x2 of the fp32 residuals
__device__ __forceinline__ void split2(float x0, float x1,
                                       uint32_t& hw, uint32_t& lw) {
    asm("cvt.rn.bf16x2.f32 %0, %1, %2;" : "=r"(hw) : "f"(x1), "f"(x0));
    float h0 = __uint_as_float(hw << 16);
    float h1 = __uint_as_float(hw & 0xFFFF0000u);
    float r0 = x0 - h0;
    float r1 = x1 - h1;
    asm("cvt.rn.bf16x2.f32 %0, %1, %2;" : "=r"(lw) : "f"(r1), "f"(r0));
}
__device__ __forceinline__ void ldm_x4(uint32_t* r, uint32_t addr) {
    asm volatile("ldmatrix.sync.aligned.m8n8.x4.shared.b16 {%0,%1,%2,%3}, [%4];"
                 : "=r"(r[0]), "=r"(r[1]), "=r"(r[2]), "=r"(r[3]) : "r"(addr));
}
__device__ __forceinline__ void ldm_x2(uint32_t* r, uint32_t addr) {
    asm volatile("ldmatrix.sync.aligned.m8n8.x2.shared.b16 {%0,%1}, [%2];"
                 : "=r"(r[0]), "=r"(r[1]) : "r"(addr));
}
__device__ __forceinline__ void mma_bf16(float* c, const uint32_t* a,
                                         const uint32_t* b) {
    asm volatile("mma.sync.aligned.m16n8k16.row.col.f32.bf16.bf16.f32 "
                 "{%0,%1,%2,%3}, {%4,%5,%6,%7}, {%8,%9}, {%0,%1,%2,%3};"
                 : "+f"(c[0]), "+f"(c[1]), "+f"(c[2]), "+f"(c[3])
                 : "r"(a[0]), "r"(a[1]), "r"(a[2]), "r"(a[3]),
                   "r"(b[0]), "r"(b[1]));
}

// ---------------------------------------------------------------------------
// Zero accumulator
// ---------------------------------------------------------------------------
__global__ void zero_acc_kernel() {
    size_t i = (size_t)blockIdx.x * blockDim.x + threadIdx.x;
    size_t n4 = (size_t)NNODES * KACC / 4;
    if (i < n4)
        reinterpret_cast<float4*>(g_acc)[i] = make_float4(0.f, 0.f, 0.f, 0.f);
}

// ---------------------------------------------------------------------------
// Edge scatter: acc[dst][et*128 + :] += x[src][:]   (one warp per edge)
// ---------------------------------------------------------------------------
__global__ void scatter_kernel(const float* __restrict__ xsrc, int use_h,
                               const int* __restrict__ src,
                               const int* __restrict__ dst,
                               const int* __restrict__ et) {
    int warp = (blockIdx.x * blockDim.x + threadIdx.x) >> 5;
    if (warp >= EDGES) return;
    int lane = threadIdx.x & 31;

    const float* xp = use_h ? g_h : xsrc;
    int s = src[warp];
    int d = dst[warp];
    int r = et[warp];

    float4 v = reinterpret_cast<const float4*>(xp + (size_t)s * DHID)[lane];
    float* p = g_acc + (size_t)d * KACC + r * DHID + lane * 4;
    asm volatile("red.global.add.v4.f32 [%0], {%1,%2,%3,%4};"
                 :: "l"(p), "f"(v.x), "f"(v.y), "f"(v.z), "f"(v.w)
                 : "memory");
}

// ---------------------------------------------------------------------------
// Pre-split weights into transposed bf16 hi/lo:  Bt[l][n][k] = Bstack_l[k][n]
// ---------------------------------------------------------------------------
__global__ void prep_B_kernel(const float* __restrict__ W1,
                              const float* __restrict__ L1,
                              const float* __restrict__ W2,
                              const float* __restrict__ L2) {
    int t = blockIdx.x * blockDim.x + threadIdx.x;
    if (t >= 2 * DHID * KTOT) return;
    int l   = t / (DHID * KTOT);
    int rem = t % (DHID * KTOT);
    int n = rem / KTOT;
    int k = rem % KTOT;
    const float* W = l ? W2 : W1;
    const float* L = l ? L2 : L1;
    float v = (k < KACC) ? W[(size_t)k * DHID + n]
                         : L[(size_t)(k - KACC) * DHID + n];
    __nv_bfloat16 h = __float2bfloat16(v);
    float r = v - __bfloat162float(h);
    g_Bth[l][rem] = h;
    g_Btl[l][rem] = __float2bfloat16(r);
}

// ---------------------------------------------------------------------------
// Warp-MMA GEMM: out = epi( [g_acc | xin] @ Bstack + bias )
// 128x128 CTA tile; 8 warps (4 along M x 2 along N); warp tile 32x64.
// mma.sync m16n8k16 bf16, 3-term split for fp32 accuracy.
// smem: Ah | Al | Bh | Bl, each [128][72] bf16 (padded rows, conflict-free).
// ---------------------------------------------------------------------------
__global__ void __launch_bounds__(256, 1)
gemm_mma_kernel(const float* __restrict__ xin, int xin_is_h, int layer,
                const float* __restrict__ bias,
                float* __restrict__ out, int out_is_h, int do_norm) {
    extern __shared__ char smem[];
    uint32_t sb = smem_u32(smem);
    const uint32_t oAh = 0, oAl = TILE_BYTES, oBh = 2 * TILE_BYTES,
                   oBl = 3 * TILE_BYTES;

    int tid  = threadIdx.x;
    int wid  = tid >> 5;
    int lane = tid & 31;
    int wm   = wid & 3;          // warp row group: rows wm*32 .. +31
    int wn   = wid >> 2;         // warp col group: cols wn*64 .. +63
    int row0 = blockIdx.x * BM;

    const float* xp = xin_is_h ? g_h : xin;
    float*       op = out_is_h ? g_h : out;
    const __nv_bfloat16* Bh = g_Bth[layer];
    const __nv_bfloat16* Bl = g_Btl[layer];

    // loader role: r = row (0..127), half = which 32-k half of the 64-k chunk
    int r    = tid >> 1;
    int half = tid & 1;
    int gr   = row0 + r;
    bool valid = gr < NNODES;

    // accumulators: [mt][nt][4]  (mt: 2 m16 tiles, nt: 8 n8 tiles)
    float acc[2][8][4];
#pragma unroll
    for (int mt = 0; mt < 2; mt++)
#pragma unroll
        for (int nt = 0; nt < 8; nt++)
#pragma unroll
            for (int j = 0; j < 4; j++) acc[mt][nt][j] = 0.f;

    // ldmatrix source addresses (fixed per thread)
    // A frag (x4): row = wm*32 + mt*16 + (lane&15), kcol = ks*16 + (lane>>4)*8
    uint32_t aoff0 = (uint32_t)((wm * 32 + (lane & 15)) * LDSB * 2
                                + (lane >> 4) * 8 * 2);
    // B frag (x2): n = wn*64 + nt*8 + (lane&7), kcol = ks*16 + ((lane>>3)&1)*8
    uint32_t boff0 = (uint32_t)((wn * 64 + (lane & 7)) * LDSB * 2
                                + ((lane >> 3) & 1) * 8 * 2);

    // A prefetch registers (32 floats = this thread's 32-k slice of its row)
    float4 apf[8];
    {
        const float4* ap = (const float4*)(g_acc + (size_t)gr * KACC + half * 32);
#pragma unroll
        for (int q = 0; q < 8; q++)
            apf[q] = valid ? ap[q] : make_float4(0.f, 0.f, 0.f, 0.f);
    }

#pragma unroll 1
    for (int c = 0; c < NCH; ++c) {
        int k0 = c * KC;
        __syncthreads();   // previous chunk's MMAs done; smem reusable

        // ---- store A (split fp32 -> bf16 hi/lo) ----
        {
            uint32_t base = (uint32_t)(r * LDSB * 2 + (half * 32) * 2);
#pragma unroll
            for (int q = 0; q < 4; q++) {
                float4 f0 = apf[2 * q], f1 = apf[2 * q + 1];
                uint4 hv, lv;
                split2(f0.x, f0.y, hv.x, lv.x);
                split2(f0.z, f0.w, hv.y, lv.y);
                split2(f1.x, f1.y, hv.z, lv.z);
                split2(f1.z, f1.w, hv.w, lv.w);
                uint32_t o = base + q * 16;
                sts128(sb + oAh + o, hv);
                sts128(sb + oAl + o, lv);
            }
        }
        // ---- load+store B (pre-split bf16, L2-resident) ----
        {
            const uint4* bhp = (const uint4*)(Bh + (size_t)r * KTOT + k0 + half * 32);
            const uint4* blp = (const uint4*)(Bl + (size_t)r * KTOT + k0 + half * 32);
            uint32_t base = (uint32_t)(r * LDSB * 2 + (half * 32) * 2);
#pragma unroll
            for (int q = 0; q < 4; q++) {
                uint32_t o = base + q * 16;
                sts128(sb + oBh + o, bhp[q]);
                sts128(sb + oBl + o, blp[q]);
            }
        }
        __syncthreads();

        // ---- prefetch next chunk's A (overlaps with MMA below) ----
        if (c + 1 < NCH) {
            int k1 = (c + 1) * KC;
            const float4* ap;
            if (k1 < KACC)
                ap = (const float4*)(g_acc + (size_t)gr * KACC + k1 + half * 32);
            else
                ap = (const float4*)(xp + (size_t)gr * DHID + (k1 - KACC) + half * 32);
#pragma unroll
            for (int q = 0; q < 8; q++)
                apf[q] = valid ? ap[q] : make_float4(0.f, 0.f, 0.f, 0.f);
        }

        // ---- MMA on this chunk: 4 k16-steps ----
#pragma unroll
        for (int ks = 0; ks < 4; ++ks) {
            uint32_t ka = (uint32_t)(ks * 16 * 2);
            uint32_t ah[2][4], al[2][4];
#pragma unroll
            for (int mt = 0; mt < 2; mt++) {
                uint32_t ao = aoff0 + (uint32_t)(mt * 16 * LDSB * 2) + ka;
                ldm_x4(ah[mt], sb + oAh + ao);
                ldm_x4(al[mt], sb + oAl + ao);
            }
#pragma unroll
            for (int nt = 0; nt < 8; nt++) {
                uint32_t bo = boff0 + (uint32_t)(nt * 8 * LDSB * 2) + ka;
                uint32_t bh2[2], bl2[2];
                ldm_x2(bh2, sb + oBh + bo);
                ldm_x2(bl2, sb + oBl + bo);
#pragma unroll
                for (int mt = 0; mt < 2; mt++) {
                    mma_bf16(acc[mt][nt], ah[mt], bh2);
                    mma_bf16(acc[mt][nt], ah[mt], bl2);
                    mma_bf16(acc[mt][nt], al[mt], bh2);
                }
            }
        }
    }
    __syncthreads();   // smem free for rowsq reuse

    // ---- epilogue ----
    int qrow = lane >> 2;          // 0..7
    int qcol = (lane & 3) * 2;     // 0,2,4,6

    // bias add
#pragma unroll
    for (int nt = 0; nt < 8; nt++) {
        int c0 = wn * 64 + nt * 8 + qcol;
        float bx = bias[c0], by = bias[c0 + 1];
#pragma unroll
        for (int mt = 0; mt < 2; mt++) {
            acc[mt][nt][0] += bx; acc[mt][nt][1] += by;
            acc[mt][nt][2] += bx; acc[mt][nt][3] += by;
        }
    }

    if (!do_norm) {
#pragma unroll
        for (int mt = 0; mt < 2; mt++)
#pragma unroll
            for (int h = 0; h < 2; h++) {
                int row = wm * 32 + mt * 16 + h * 8 + qrow;
                int g = row0 + row;
                if (g < NNODES) {
#pragma unroll
                    for (int nt = 0; nt < 8; nt++) {
                        int c0 = wn * 64 + nt * 8 + qcol;
                        float2 v = make_float2(fmaxf(acc[mt][nt][h * 2], 0.f),
                                               fmaxf(acc[mt][nt][h * 2 + 1], 0.f));
                        *(float2*)(op + (size_t)g * DHID + c0) = v;
                    }
                }
            }
    } else {
        float* rowsq = (float*)smem;
        if (tid < BM) rowsq[tid] = 0.f;
        __syncthreads();
        float s[2][2];
#pragma unroll
        for (int mt = 0; mt < 2; mt++)
#pragma unroll
            for (int h = 0; h < 2; h++) {
                float t = 0.f;
#pragma unroll
                for (int nt = 0; nt < 8; nt++) {
                    t += acc[mt][nt][h * 2] * acc[mt][nt][h * 2]
                       + acc[mt][nt][h * 2 + 1] * acc[mt][nt][h * 2 + 1];
                }
                t += __shfl_xor_sync(0xFFFFFFFFu, t, 1);
                t += __shfl_xor_sync(0xFFFFFFFFu, t, 2);
                s[mt][h] = t;
            }
        if ((lane & 3) == 0) {
#pragma unroll
            for (int mt = 0; mt < 2; mt++)
#pragma unroll
                for (int h = 0; h < 2; h++)
                    atomicAdd(&rowsq[wm * 32 + mt * 16 + h * 8 + qrow], s[mt][h]);
        }
        __syncthreads();
#pragma unroll
        for (int mt = 0; mt < 2; mt++)
#pragma unroll
            for (int h = 0; h < 2; h++) {
                int row = wm * 32 + mt * 16 + h * 8 + qrow;
                int g = row0 + row;
                if (g < NNODES) {
                    float inv = 1.0f / fmaxf(sqrtf(rowsq[row]), 1e-12f);
#pragma unroll
                    for (int nt = 0; nt < 8; nt++) {
                        int c0 = wn * 64 + nt * 8 + qcol;
                        float2 v = make_float2(acc[mt][nt][h * 2] * inv,
                                               acc[mt][nt][h * 2 + 1] * inv);
                        *(float2*)(op + (size_t)g * DHID + c0) = v;
                    }
                }
            }
    }
}

// ---------------------------------------------------------------------------
// Launch
// ---------------------------------------------------------------------------
extern "C" void kernel_launch(void* const* d_in, const int* in_sizes, int n_in,
                              void* d_out, int out_size) {
    const float* x      = (const float*)d_in[0];
    const float* W1     = (const float*)d_in[1];
    const float* loopW1 = (const float*)d_in[2];
    const float* b1     = (const float*)d_in[3];
    const float* W2     = (const float*)d_in[4];
    const float* loopW2 = (const float*)d_in[5];
    const float* b2     = (const float*)d_in[6];
    const int*   src    = (const int*)d_in[7];
    const int*   dst    = (const int*)d_in[8];
    const int*   et     = (const int*)d_in[9];
    float* out = (float*)d_out;

    cudaFuncSetAttribute(gemm_mma_kernel,
                         cudaFuncAttributeMaxDynamicSharedMemorySize, SMEM_BYTES);

    int zblocks = (int)(((size_t)NNODES * KACC / 4 + 255) / 256);
    int sblocks = (int)(((size_t)EDGES * 32 + 255) / 256);
    int gblocks = (NNODES + BM - 1) / BM;                   // 391
    int pblocks = (2 * DHID * KTOT + 255) / 256;

    prep_B_kernel<<<pblocks, 256>>>(W1, loopW1, W2, loopW2);

    // Layer 1
    zero_acc_kernel<<<zblocks, 256>>>();
    scatter_kernel<<<sblocks, 256>>>(x, 0, src, dst, et);
    gemm_mma_kernel<<<gblocks, 256, SMEM_BYTES>>>(x, 0, 0, b1, nullptr, 1, 0);

    // Layer 2
    zero_acc_kernel<<<zblocks, 256>>>();
    scatter_kernel<<<sblocks, 256>>>(nullptr, 1, src, dst, et);
    gemm_mma_kernel<<<gblocks, 256, SMEM_BYTES>>>(nullptr, 1, 1, b2, out, 0, 1);
}

// round 5
// speedup vs baseline: 1.7783x; 1.1435x over previous
#include <cuda_runtime.h>
#include <cuda_bf16.h>
#include <cstdint>

#define NNODES 50000
#define EDGES  800000
#define DHID   128
#define RREL   8
#define KACC   (RREL * DHID)   /* 1024 */
#define KTOT   (KACC + DHID)   /* 1152 */

#define BM   128               /* CTA tile rows */
#define KC   64                /* K chunk       */
#define NCH  (KTOT / KC)       /* 18            */
#define LDSB 72                /* padded row length in bf16 elements (144 B) */
#define TILE_BYTES (128 * LDSB * 2)        /* 18432 per buffer */
#define STAGE_BYTES (4 * TILE_BYTES)       /* Ah, Al, Bh, Bl = 73728 */
#define SMEM_BYTES (2 * STAGE_BYTES)       /* double buffered = 147456 */

// ---------------------------------------------------------------------------
// Scratch (device globals — no allocation allowed)
// ---------------------------------------------------------------------------
__device__ float g_acc[(size_t)NNODES * KACC];            // 204.8 MB
__device__ float g_h[(size_t)NNODES * DHID];              // 25.6 MB
__device__ __nv_bfloat16 g_Bth[2][(size_t)DHID * KTOT];   // B^T hi  [layer][n*1152+k]
__device__ __nv_bfloat16 g_Btl[2][(size_t)DHID * KTOT];   // B^T lo

// ---------------------------------------------------------------------------
// PTX helpers (standard sm_80-level PTX only — the harness targets sm_103,
// not sm_103a, so tcgen05 is unavailable)
// ---------------------------------------------------------------------------
__device__ __forceinline__ uint32_t smem_u32(const void* p) {
    uint32_t a;
    asm("{ .reg .u64 t; cvta.to.shared.u64 t, %1; cvt.u32.u64 %0, t; }"
        : "=r"(a) : "l"(p));
    return a;
}
__device__ __forceinline__ void sts128(uint32_t a, uint4 v) {
    asm volatile("st.shared.v4.b32 [%0], {%1,%2,%3,%4};"
                 :: "r"(a), "r"(v.x), "r"(v.y), "r"(v.z), "r"(v.w) : "memory");
}
// pack (x1,x0) -> bf16x2 (x0 low), plus bf16x2 of the fp32 residuals
__device__ __forceinline__ void split2(float x0, float x1,
                                       uint32_t& hw, uint32_t& lw) {
    asm("cvt.rn.bf16x2.f32 %0, %1, %2;" : "=r"(hw) : "f"(x1), "f"(x0));
    float h0 = __uint_as_float(hw << 16);
    float h1 = __uint_as_float(hw & 0xFFFF0000u);
    float r0 = x0 - h0;
    float r1 = x1 - h1;
    asm("cvt.rn.bf16x2.f32 %0, %1, %2;" : "=r"(lw) : "f"(r1), "f"(r0));
}
__device__ __forceinline__ void ldm_x4(uint32_t* r, uint32_t addr) {
    asm volatile("ldmatrix.sync.aligned.m8n8.x4.shared.b16 {%0,%1,%2,%3}, [%4];"
                 : "=r"(r[0]), "=r"(r[1]), "=r"(r[2]), "=r"(r[3]) : "r"(addr));
}
__device__ __forceinline__ void mma_bf16(float* c, const uint32_t* a,
                                         const uint32_t* b) {
    asm volatile("mma.sync.aligned.m16n8k16.row.col.f32.bf16.bf16.f32 "
                 "{%0,%1,%2,%3}, {%4,%5,%6,%7}, {%8,%9}, {%0,%1,%2,%3};"
                 : "+f"(c[0]), "+f"(c[1]), "+f"(c[2]), "+f"(c[3])
                 : "r"(a[0]), "r"(a[1]), "r"(a[2]), "r"(a[3]),
                   "r"(b[0]), "r"(b[1]));
}

// ---------------------------------------------------------------------------
// Zero accumulator
// ---------------------------------------------------------------------------
__global__ void zero_acc_kernel() {
    size_t i = (size_t)blockIdx.x * blockDim.x + threadIdx.x;
    size_t n4 = (size_t)NNODES * KACC / 4;
    if (i < n4)
        reinterpret_cast<float4*>(g_acc)[i] = make_float4(0.f, 0.f, 0.f, 0.f);
}

// ---------------------------------------------------------------------------
// Edge scatter: acc[dst][et*128 + :] += x[src][:]   (one warp per edge)
// ---------------------------------------------------------------------------
__global__ void scatter_kernel(const float* __restrict__ xsrc, int use_h,
                               const int* __restrict__ src,
                               const int* __restrict__ dst,
                               const int* __restrict__ et) {
    int warp = (blockIdx.x * blockDim.x + threadIdx.x) >> 5;
    if (warp >= EDGES) return;
    int lane = threadIdx.x & 31;

    const float* xp = use_h ? g_h : xsrc;
    int s = src[warp];
    int d = dst[warp];
    int r = et[warp];

    float4 v = reinterpret_cast<const float4*>(xp + (size_t)s * DHID)[lane];
    float* p = g_acc + (size_t)d * KACC + r * DHID + lane * 4;
    asm volatile("red.global.add.v4.f32 [%0], {%1,%2,%3,%4};"
                 :: "l"(p), "f"(v.x), "f"(v.y), "f"(v.z), "f"(v.w)
                 : "memory");
}

// ---------------------------------------------------------------------------
// Pre-split weights into transposed bf16 hi/lo:  Bt[l][n][k] = Bstack_l[k][n]
// ---------------------------------------------------------------------------
__global__ void prep_B_kernel(const float* __restrict__ W1,
                              const float* __restrict__ L1,
                              const float* __restrict__ W2,
                              const float* __restrict__ L2) {
    int t = blockIdx.x * blockDim.x + threadIdx.x;
    if (t >= 2 * DHID * KTOT) return;
    int l   = t / (DHID * KTOT);
    int rem = t % (DHID * KTOT);
    int n = rem / KTOT;
    int k = rem % KTOT;
    const float* W = l ? W2 : W1;
    const float* L = l ? L2 : L1;
    float v = (k < KACC) ? W[(size_t)k * DHID + n]
                         : L[(size_t)(k - KACC) * DHID + n];
    __nv_bfloat16 h = __float2bfloat16(v);
    float r = v - __bfloat162float(h);
    g_Bth[l][rem] = h;
    g_Btl[l][rem] = __float2bfloat16(r);
}

// ---------------------------------------------------------------------------
// Warp-MMA GEMM, double-buffered: out = epi( [g_acc | xin] @ Bstack + bias )
// 128x128 CTA tile; 8 warps (4 M x 2 N); warp tile 32x64.
// mma.sync m16n8k16 bf16, 3-term split for fp32 accuracy.
// Per stage: Ah | Al | Bh | Bl, each [128][72] bf16 (padded, conflict-free).
// ---------------------------------------------------------------------------
__global__ void __launch_bounds__(256, 1)
gemm_mma_kernel(const float* __restrict__ xin, int xin_is_h, int layer,
                const float* __restrict__ bias,
                float* __restrict__ out, int out_is_h, int do_norm) {
    extern __shared__ char smem[];
    uint32_t sb = smem_u32(smem);

    int tid  = threadIdx.x;
    int wid  = tid >> 5;
    int lane = tid & 31;
    int wm   = wid & 3;          // warp row group: rows wm*32 .. +31
    int wn   = wid >> 2;         // warp col group: cols wn*64 .. +63
    int row0 = blockIdx.x * BM;

    const float* xp = xin_is_h ? g_h : xin;
    float*       op = out_is_h ? g_h : out;
    const __nv_bfloat16* Bhg = g_Bth[layer];
    const __nv_bfloat16* Blg = g_Btl[layer];

    // loader role: r = row (0..127), half = which 32-k half of the 64-k chunk
    int r    = tid >> 1;
    int half = tid & 1;
    int gr   = row0 + r;
    bool valid = gr < NNODES;

    float acc[2][8][4];
#pragma unroll
    for (int mt = 0; mt < 2; mt++)
#pragma unroll
        for (int nt = 0; nt < 8; nt++)
#pragma unroll
            for (int j = 0; j < 4; j++) acc[mt][nt][j] = 0.f;

    // ldmatrix source offsets (fixed per thread)
    // A frag (x4): row = wm*32 + mt*16 + (lane&15), kcol = ks*16 + (lane>>4)*8
    uint32_t aoff0 = (uint32_t)((wm * 32 + (lane & 15)) * LDSB * 2
                                + (lane >> 4) * 8 * 2);
    // B pair frag (x4): matrices {ntp k0},{ntp k8},{ntp+1 k0},{ntp+1 k8}
    uint32_t boff0 = (uint32_t)((wn * 64 + ((lane >> 4) & 1) * 8 + (lane & 7))
                                * LDSB * 2 + ((lane >> 3) & 1) * 16);

    uint32_t sbase = (uint32_t)(r * LDSB * 2 + half * 64);  // store offset in tile

    // ---- register prefetch buffers ----
    float4 apf[8];
    uint4  bhf[4], blf[4];

    auto prefetch = [&](int c) {
        int k0 = c * KC;
        const float4* ap = (k0 < KACC)
            ? (const float4*)(g_acc + (size_t)gr * KACC + k0 + half * 32)
            : (const float4*)(xp + (size_t)gr * DHID + (k0 - KACC) + half * 32);
#pragma unroll
        for (int q = 0; q < 8; q++)
            apf[q] = valid ? ap[q] : make_float4(0.f, 0.f, 0.f, 0.f);
        const uint4* bhp = (const uint4*)(Bhg + (size_t)r * KTOT + k0 + half * 32);
        const uint4* blp = (const uint4*)(Blg + (size_t)r * KTOT + k0 + half * 32);
#pragma unroll
        for (int q = 0; q < 4; q++) { bhf[q] = bhp[q]; blf[q] = blp[q]; }
    };

    auto store_stage = [&](int s) {
        uint32_t st = sb + (uint32_t)s * STAGE_BYTES;
#pragma unroll
        for (int q = 0; q < 4; q++) {
            float4 f0 = apf[2 * q], f1 = apf[2 * q + 1];
            uint4 hv, lv;
            split2(f0.x, f0.y, hv.x, lv.x);
            split2(f0.z, f0.w, hv.y, lv.y);
            split2(f1.x, f1.y, hv.z, lv.z);
            split2(f1.z, f1.w, hv.w, lv.w);
            uint32_t o = sbase + q * 16;
            sts128(st + o, hv);
            sts128(st + TILE_BYTES + o, lv);
            sts128(st + 2 * TILE_BYTES + o, bhf[q]);
            sts128(st + 3 * TILE_BYTES + o, blf[q]);
        }
    };

    // ---- prologue: chunk 0 into stage 0; prefetch chunk 1 ----
    prefetch(0);
    store_stage(0);
    prefetch(1);
    __syncthreads();

#pragma unroll 1
    for (int c = 0; c < NCH; ++c) {
        int s = c & 1;
        uint32_t st = sb + (uint32_t)s * STAGE_BYTES;

        // ---- MMA on stage s ----
#pragma unroll
        for (int ks = 0; ks < 4; ++ks) {
            uint32_t ka = (uint32_t)(ks * 32);
            uint32_t ah[2][4], al[2][4];
#pragma unroll
            for (int mt = 0; mt < 2; mt++) {
                uint32_t ao = aoff0 + (uint32_t)(mt * 16 * LDSB * 2) + ka;
                ldm_x4(ah[mt], st + ao);
                ldm_x4(al[mt], st + TILE_BYTES + ao);
            }
#pragma unroll
            for (int ntp = 0; ntp < 4; ntp++) {
                uint32_t bo = boff0 + (uint32_t)(ntp * 16 * LDSB * 2) + ka;
                uint32_t bh4[4], bl4[4];
                ldm_x4(bh4, st + 2 * TILE_BYTES + bo);
                ldm_x4(bl4, st + 3 * TILE_BYTES + bo);
#pragma unroll
                for (int mt = 0; mt < 2; mt++) {
                    mma_bf16(acc[mt][2 * ntp],     ah[mt], bh4);
                    mma_bf16(acc[mt][2 * ntp],     ah[mt], bl4);
                    mma_bf16(acc[mt][2 * ntp],     al[mt], bh4);
                    mma_bf16(acc[mt][2 * ntp + 1], ah[mt], bh4 + 2);
                    mma_bf16(acc[mt][2 * ntp + 1], ah[mt], bl4 + 2);
                    mma_bf16(acc[mt][2 * ntp + 1], al[mt], bh4 + 2);
                }
            }
        }

        // ---- store chunk c+1 into the other stage; prefetch c+2 ----
        if (c + 1 < NCH) {
            store_stage(s ^ 1);
            if (c + 2 < NCH) prefetch(c + 2);
        }
        __syncthreads();
    }

    // ---- epilogue ----
    int qrow = lane >> 2;          // 0..7
    int qcol = (lane & 3) * 2;     // 0,2,4,6

#pragma unroll
    for (int nt = 0; nt < 8; nt++) {
        int c0 = wn * 64 + nt * 8 + qcol;
        float bx = bias[c0], by = bias[c0 + 1];
#pragma unroll
        for (int mt = 0; mt < 2; mt++) {
            acc[mt][nt][0] += bx; acc[mt][nt][1] += by;
            acc[mt][nt][2] += bx; acc[mt][nt][3] += by;
        }
    }

    if (!do_norm) {
#pragma unroll
        for (int mt = 0; mt < 2; mt++)
#pragma unroll
            for (int h = 0; h < 2; h++) {
                int row = wm * 32 + mt * 16 + h * 8 + qrow;
                int g = row0 + row;
                if (g < NNODES) {
#pragma unroll
                    for (int nt = 0; nt < 8; nt++) {
                        int c0 = wn * 64 + nt * 8 + qcol;
                        float2 v = make_float2(fmaxf(acc[mt][nt][h * 2], 0.f),
                                               fmaxf(acc[mt][nt][h * 2 + 1], 0.f));
                        *(float2*)(op + (size_t)g * DHID + c0) = v;
                    }
                }
            }
    } else {
        float* rowsq = (float*)smem;
        if (tid < BM) rowsq[tid] = 0.f;
        __syncthreads();
        float s2[2][2];
#pragma unroll
        for (int mt = 0; mt < 2; mt++)
#pragma unroll
            for (int h = 0; h < 2; h++) {
                float t = 0.f;
#pragma unroll
                for (int nt = 0; nt < 8; nt++) {
                    t += acc[mt][nt][h * 2] * acc[mt][nt][h * 2]
                       + acc[mt][nt][h * 2 + 1] * acc[mt][nt][h * 2 + 1];
                }
                t += __shfl_xor_sync(0xFFFFFFFFu, t, 1);
                t += __shfl_xor_sync(0xFFFFFFFFu, t, 2);
                s2[mt][h] = t;
            }
        if ((lane & 3) == 0) {
#pragma unroll
            for (int mt = 0; mt < 2; mt++)
#pragma unroll
                for (int h = 0; h < 2; h++)
                    atomicAdd(&rowsq[wm * 32 + mt * 16 + h * 8 + qrow], s2[mt][h]);
        }
        __syncthreads();
#pragma unroll
        for (int mt = 0; mt < 2; mt++)
#pragma unroll
            for (int h = 0; h < 2; h++) {
                int row = wm * 32 + mt * 16 + h * 8 + qrow;
                int g = row0 + row;
                if (g < NNODES) {
                    float inv = 1.0f / fmaxf(sqrtf(rowsq[row]), 1e-12f);
#pragma unroll
                    for (int nt = 0; nt < 8; nt++) {
                        int c0 = wn * 64 + nt * 8 + qcol;
                        float2 v = make_float2(acc[mt][nt][h * 2] * inv,
                                               acc[mt][nt][h * 2 + 1] * inv);
                        *(float2*)(op + (size_t)g * DHID + c0) = v;
                    }
                }
            }
    }
}

// ---------------------------------------------------------------------------
// Launch
// ---------------------------------------------------------------------------
extern "C" void kernel_launch(void* const* d_in, const int* in_sizes, int n_in,
                              void* d_out, int out_size) {
    const float* x      = (const float*)d_in[0];
    const float* W1     = (const float*)d_in[1];
    const float* loopW1 = (const float*)d_in[2];
    const float* b1     = (const float*)d_in[3];
    const float* W2     = (const float*)d_in[4];
    const float* loopW2 = (const float*)d_in[5];
    const float* b2     = (const float*)d_in[6];
    const int*   src    = (const int*)d_in[7];
    const int*   dst    = (const int*)d_in[8];
    const int*   et     = (const int*)d_in[9];
    float* out = (float*)d_out;

    cudaFuncSetAttribute(gemm_mma_kernel,
                         cudaFuncAttributeMaxDynamicSharedMemorySize, SMEM_BYTES);

    int zblocks = (int)(((size_t)NNODES * KACC / 4 + 255) / 256);
    int sblocks = (int)(((size_t)EDGES * 32 + 255) / 256);
    int gblocks = (NNODES + BM - 1) / BM;                   // 391
    int pblocks = (2 * DHID * KTOT + 255) / 256;

    prep_B_kernel<<<pblocks, 256>>>(W1, loopW1, W2, loopW2);

    // Layer 1
    zero_acc_kernel<<<zblocks, 256>>>();
    scatter_kernel<<<sblocks, 256>>>(x, 0, src, dst, et);
    gemm_mma_kernel<<<gblocks, 256, SMEM_BYTES>>>(x, 0, 0, b1, nullptr, 1, 0);

    // Layer 2
    zero_acc_kernel<<<zblocks, 256>>>();
    scatter_kernel<<<sblocks, 256>>>(nullptr, 1, src, dst, et);
    gemm_mma_kernel<<<gblocks, 256, SMEM_BYTES>>>(nullptr, 1, 1, b2, out, 0, 1);
}

// round 7
// speedup vs baseline: 1.9928x; 1.1206x over previous
#include <cuda_runtime.h>
#include <cuda_bf16.h>
#include <cstdint>

#define NNODES 50000
#define EDGES  800000
#define DHID   128
#define RREL   8
#define KACC   (RREL * DHID)   /* 1024 */
#define KTOT   (KACC + DHID)   /* 1152 */
#define NR     (NNODES * RREL) /* 400000 buckets */
#define NBLK1  ((NR + 1023) / 1024)  /* 391 */

#define BM   128
#define KC   64
#define NCH  (KTOT / KC)       /* 18 */
#define LDSB 72
#define TILE_BYTES (128 * LDSB * 2)
#define STAGE_BYTES (4 * TILE_BYTES)
#define SMEM_BYTES (2 * STAGE_BYTES)

// ---------------------------------------------------------------------------
// Scratch
// ---------------------------------------------------------------------------
__device__ float g_h[(size_t)NNODES * DHID];              // layer-1 output
__device__ __nv_bfloat16 g_Bth[2][(size_t)DHID * KTOT];
__device__ __nv_bfloat16 g_Btl[2][(size_t)DHID * KTOT];
__device__ int g_off[NR];      // CSR bucket starts (exclusive scan)
__device__ int g_cnt[NR];      // counts -> cursor -> bucket ENDS after fill
__device__ int g_csr[EDGES];   // src node per slot
__device__ int g_bsum[512];

// ---------------------------------------------------------------------------
// PTX helpers (standard PTX only — harness targets sm_103, no "a" features)
// ---------------------------------------------------------------------------
__device__ __forceinline__ uint32_t smem_u32(const void* p) {
    uint32_t a;
    asm("{ .reg .u64 t; cvta.to.shared.u64 t, %1; cvt.u32.u64 %0, t; }"
        : "=r"(a) : "l"(p));
    return a;
}
__device__ __forceinline__ void sts128(uint32_t a, uint4 v) {
    asm volatile("st.shared.v4.b32 [%0], {%1,%2,%3,%4};"
                 :: "r"(a), "r"(v.x), "r"(v.y), "r"(v.z), "r"(v.w) : "memory");
}
__device__ __forceinline__ void split2(float x0, float x1,
                                       uint32_t& hw, uint32_t& lw) {
    asm("cvt.rn.bf16x2.f32 %0, %1, %2;" : "=r"(hw) : "f"(x1), "f"(x0));
    float h0 = __uint_as_float(hw << 16);
    float h1 = __uint_as_float(hw & 0xFFFF0000u);
    float r0 = x0 - h0;
    float r1 = x1 - h1;
    asm("cvt.rn.bf16x2.f32 %0, %1, %2;" : "=r"(lw) : "f"(r1), "f"(r0));
}
__device__ __forceinline__ void ldm_x4(uint32_t* r, uint32_t addr) {
    asm volatile("ldmatrix.sync.aligned.m8n8.x4.shared.b16 {%0,%1,%2,%3}, [%4];"
                 : "=r"(r[0]), "=r"(r[1]), "=r"(r[2]), "=r"(r[3]) : "r"(addr));
}
__device__ __forceinline__ void mma_bf16(float* c, const uint32_t* a,
                                         const uint32_t* b) {
    asm volatile("mma.sync.aligned.m16n8k16.row.col.f32.bf16.bf16.f32 "
                 "{%0,%1,%2,%3}, {%4,%5,%6,%7}, {%8,%9}, {%0,%1,%2,%3};"
                 : "+f"(c[0]), "+f"(c[1]), "+f"(c[2]), "+f"(c[3])
                 : "r"(a[0]), "r"(a[1]), "r"(a[2]), "r"(a[3]),
                   "r"(b[0]), "r"(b[1]));
}

// ---------------------------------------------------------------------------
// CSR build kernels
// ---------------------------------------------------------------------------
__global__ void zero_cnt_kernel() {
    int i = blockIdx.x * blockDim.x + threadIdx.x;   // i in [0, NR/4)
    if (i * 4 < NR)
        *reinterpret_cast<int4*>(g_cnt + i * 4) = make_int4(0, 0, 0, 0);
}
__global__ void hist_kernel(const int* __restrict__ dst,
                            const int* __restrict__ et) {
    int e = blockIdx.x * blockDim.x + threadIdx.x;
    if (e < EDGES) atomicAdd(&g_cnt[dst[e] * RREL + et[e]], 1);
}
__global__ void scan1_kernel() {
    __shared__ int wsum[8];
    int tid = threadIdx.x;
    int base = blockIdx.x * 1024 + tid * 4;
    int v[4];
#pragma unroll
    for (int q = 0; q < 4; q++)
        v[q] = (base + q < NR) ? g_cnt[base + q] : 0;
    int s = v[0] + v[1] + v[2] + v[3];
    int lane = tid & 31, w = tid >> 5;
    int inc = s;
#pragma unroll
    for (int d = 1; d < 32; d <<= 1) {
        int t = __shfl_up_sync(0xFFFFFFFFu, inc, d);
        if (lane >= d) inc += t;
    }
    if (lane == 31) wsum[w] = inc;
    __syncthreads();
    if (tid == 0) {
        int a = 0;
#pragma unroll
        for (int i = 0; i < 8; i++) { int t = wsum[i]; wsum[i] = a; a += t; }
        g_bsum[blockIdx.x] = a;
    }
    __syncthreads();
    int ex = inc - s + wsum[w];
#pragma unroll
    for (int q = 0; q < 4; q++) {
        if (base + q < NR) g_off[base + q] = ex;
        ex += v[q];
    }
}
__global__ void scan2_kernel() {      // 512 threads, scans g_bsum[NBLK1]
    __shared__ int sm[512];
    int tid = threadIdx.x;
    int v = (tid < NBLK1) ? g_bsum[tid] : 0;
    sm[tid] = v;
    __syncthreads();
    for (int d = 1; d < 512; d <<= 1) {
        int t = (tid >= d) ? sm[tid - d] : 0;
        __syncthreads();
        sm[tid] += t;
        __syncthreads();
    }
    if (tid < NBLK1) g_bsum[tid] = sm[tid] - v;   // exclusive
}
__global__ void scan3_kernel() {
    int i = blockIdx.x * blockDim.x + threadIdx.x;
    if (i < NR) {
        int o = g_off[i] + g_bsum[i >> 10];
        g_off[i] = o;
        g_cnt[i] = o;      // cursor for fill; becomes bucket END after fill
    }
}
__global__ void fill_kernel(const int* __restrict__ src,
                            const int* __restrict__ dst,
                            const int* __restrict__ et) {
    int e = blockIdx.x * blockDim.x + threadIdx.x;
    if (e < EDGES) {
        int b = dst[e] * RREL + et[e];
        int pos = atomicAdd(&g_cnt[b], 1);
        g_csr[pos] = src[e];
    }
}

// ---------------------------------------------------------------------------
// Pre-split weights: Bt[l][n][k] = Bstack_l[k][n]  (hi/lo bf16)
// ---------------------------------------------------------------------------
__global__ void prep_B_kernel(const float* __restrict__ W1,
                              const float* __restrict__ L1,
                              const float* __restrict__ W2,
                              const float* __restrict__ L2) {
    int t = blockIdx.x * blockDim.x + threadIdx.x;
    if (t >= 2 * DHID * KTOT) return;
    int l   = t / (DHID * KTOT);
    int rem = t % (DHID * KTOT);
    int n = rem / KTOT;
    int k = rem % KTOT;
    const float* W = l ? W2 : W1;
    const float* L = l ? L2 : L1;
    float v = (k < KACC) ? W[(size_t)k * DHID + n]
                         : L[(size_t)(k - KACC) * DHID + n];
    __nv_bfloat16 h = __float2bfloat16(v);
    float r = v - __bfloat162float(h);
    g_Bth[l][rem] = h;
    g_Btl[l][rem] = __float2bfloat16(r);
}

// ---------------------------------------------------------------------------
// Fused gather + warp-MMA GEMM, double-buffered.
//   A row n, chunk c<16 (rel r=c>>1): sum_{e in CSR[n*8+r]} x[src_e][slice]
//   chunks 16,17: self-loop slice of input row.
// ---------------------------------------------------------------------------
__global__ void __launch_bounds__(256, 1)
gemm_mma_kernel(const float* __restrict__ xin, int xin_is_h, int layer,
                const float* __restrict__ bias,
                float* __restrict__ out, int out_is_h, int do_norm) {
    extern __shared__ char smem[];
    uint32_t sb = smem_u32(smem);

    int tid  = threadIdx.x;
    int wid  = tid >> 5;
    int lane = tid & 31;
    int wm   = wid & 3;
    int wn   = wid >> 2;
    int row0 = blockIdx.x * BM;

    const float* xp = xin_is_h ? g_h : xin;
    float*       op = out_is_h ? g_h : out;
    const __nv_bfloat16* Bhg = g_Bth[layer];
    const __nv_bfloat16* Blg = g_Btl[layer];

    int r    = tid >> 1;     // loader row 0..127
    int half = tid & 1;      // 32-wide sub-slice within the 64-k chunk
    int gr   = row0 + r;
    bool valid = gr < NNODES;
    int grc = valid ? gr : 0;

    float acc[2][8][4];
#pragma unroll
    for (int mt = 0; mt < 2; mt++)
#pragma unroll
        for (int nt = 0; nt < 8; nt++)
#pragma unroll
            for (int j = 0; j < 4; j++) acc[mt][nt][j] = 0.f;

    uint32_t aoff0 = (uint32_t)((wm * 32 + (lane & 15)) * LDSB * 2
                                + (lane >> 4) * 8 * 2);
    uint32_t boff0 = (uint32_t)((wn * 64 + ((lane >> 4) & 1) * 8 + (lane & 7))
                                * LDSB * 2 + ((lane >> 3) & 1) * 16);
    uint32_t sbase = (uint32_t)(r * LDSB * 2 + half * 64);

    // ---- lookahead registers ----
    uint4 bhf[4], blf[4];    // B hi/lo for the chunk about to be produced
    int rs = 0, re = 0;      // CSR range for that chunk

    auto prefetch_meta = [&](int c) {
        int k0 = c * KC;
        const uint4* bhp = (const uint4*)(Bhg + (size_t)r * KTOT + k0 + half * 32);
        const uint4* blp = (const uint4*)(Blg + (size_t)r * KTOT + k0 + half * 32);
#pragma unroll
        for (int q = 0; q < 4; q++) { bhf[q] = bhp[q]; blf[q] = blp[q]; }
        if (c < 16 && valid) {
            int b = grc * RREL + (c >> 1);
            rs = g_off[b];
            re = g_cnt[b];
        } else {
            rs = re = 0;
        }
    };

    auto produce_store = [&](int c, int s) {
        // gather / self-loop into sv
        float4 sv[8];
#pragma unroll
        for (int q = 0; q < 8; q++) sv[q] = make_float4(0.f, 0.f, 0.f, 0.f);
        int ih = c & 1;
        const float* xb = xp + ih * 64 + half * 32;
        if (c < 16) {
#pragma unroll 2
            for (int e = rs; e < re; e++) {
                int sidx = g_csr[e];
                const float4* p = (const float4*)(xb + (size_t)sidx * DHID);
#pragma unroll
                for (int q = 0; q < 8; q++) {
                    float4 t = p[q];
                    sv[q].x += t.x; sv[q].y += t.y;
                    sv[q].z += t.z; sv[q].w += t.w;
                }
            }
        } else if (valid) {
            const float4* p = (const float4*)(xb + (size_t)grc * DHID);
#pragma unroll
            for (int q = 0; q < 8; q++) sv[q] = p[q];
        }
        // split + store A and B
        uint32_t st = sb + (uint32_t)s * STAGE_BYTES;
#pragma unroll
        for (int q = 0; q < 4; q++) {
            float4 f0 = sv[2 * q], f1 = sv[2 * q + 1];
            uint4 hv, lv;
            split2(f0.x, f0.y, hv.x, lv.x);
            split2(f0.z, f0.w, hv.y, lv.y);
            split2(f1.x, f1.y, hv.z, lv.z);
            split2(f1.z, f1.w, hv.w, lv.w);
            uint32_t o = sbase + q * 16;
            sts128(st + o, hv);
            sts128(st + TILE_BYTES + o, lv);
            sts128(st + 2 * TILE_BYTES + o, bhf[q]);
            sts128(st + 3 * TILE_BYTES + o, blf[q]);
        }
    };

    // ---- prologue ----
    prefetch_meta(0);
    produce_store(0, 0);
    prefetch_meta(1);
    __syncthreads();

#pragma unroll 1
    for (int c = 0; c < NCH; ++c) {
        int s = c & 1;
        uint32_t st = sb + (uint32_t)s * STAGE_BYTES;

#pragma unroll
        for (int ks = 0; ks < 4; ++ks) {
            uint32_t ka = (uint32_t)(ks * 32);
            uint32_t ah[2][4], al[2][4];
#pragma unroll
            for (int mt = 0; mt < 2; mt++) {
                uint32_t ao = aoff0 + (uint32_t)(mt * 16 * LDSB * 2) + ka;
                ldm_x4(ah[mt], st + ao);
                ldm_x4(al[mt], st + TILE_BYTES + ao);
            }
#pragma unroll
            for (int ntp = 0; ntp < 4; ntp++) {
                uint32_t bo = boff0 + (uint32_t)(ntp * 16 * LDSB * 2) + ka;
                uint32_t bh4[4], bl4[4];
                ldm_x4(bh4, st + 2 * TILE_BYTES + bo);
                ldm_x4(bl4, st + 3 * TILE_BYTES + bo);
#pragma unroll
                for (int mt = 0; mt < 2; mt++) {
                    mma_bf16(acc[mt][2 * ntp],     ah[mt], bh4);
                    mma_bf16(acc[mt][2 * ntp],     ah[mt], bl4);
                    mma_bf16(acc[mt][2 * ntp],     al[mt], bh4);
                    mma_bf16(acc[mt][2 * ntp + 1], ah[mt], bh4 + 2);
                    mma_bf16(acc[mt][2 * ntp + 1], ah[mt], bl4 + 2);
                    mma_bf16(acc[mt][2 * ntp + 1], al[mt], bh4 + 2);
                }
            }
        }

        if (c + 1 < NCH) {
            produce_store(c + 1, s ^ 1);
            if (c + 2 < NCH) prefetch_meta(c + 2);
        }
        __syncthreads();
    }

    // ---- epilogue ----
    int qrow = lane >> 2;
    int qcol = (lane & 3) * 2;

#pragma unroll
    for (int nt = 0; nt < 8; nt++) {
        int c0 = wn * 64 + nt * 8 + qcol;
        float bx = bias[c0], by = bias[c0 + 1];
#pragma unroll
        for (int mt = 0; mt < 2; mt++) {
            acc[mt][nt][0] += bx; acc[mt][nt][1] += by;
            acc[mt][nt][2] += bx; acc[mt][nt][3] += by;
        }
    }

    if (!do_norm) {
#pragma unroll
        for (int mt = 0; mt < 2; mt++)
#pragma unroll
            for (int h = 0; h < 2; h++) {
                int row = wm * 32 + mt * 16 + h * 8 + qrow;
                int g = row0 + row;
                if (g < NNODES) {
#pragma unroll
                    for (int nt = 0; nt < 8; nt++) {
                        int c0 = wn * 64 + nt * 8 + qcol;
                        float2 v = make_float2(fmaxf(acc[mt][nt][h * 2], 0.f),
                                               fmaxf(acc[mt][nt][h * 2 + 1], 0.f));
                        *(float2*)(op + (size_t)g * DHID + c0) = v;
                    }
                }
            }
    } else {
        float* rowsq = (float*)smem;
        if (tid < BM) rowsq[tid] = 0.f;
        __syncthreads();
        float s2[2][2];
#pragma unroll
        for (int mt = 0; mt < 2; mt++)
#pragma unroll
            for (int h = 0; h < 2; h++) {
                float t = 0.f;
#pragma unroll
                for (int nt = 0; nt < 8; nt++) {
                    t += acc[mt][nt][h * 2] * acc[mt][nt][h * 2]
                       + acc[mt][nt][h * 2 + 1] * acc[mt][nt][h * 2 + 1];
                }
                t += __shfl_xor_sync(0xFFFFFFFFu, t, 1);
                t += __shfl_xor_sync(0xFFFFFFFFu, t, 2);
                s2[mt][h] = t;
            }
        if ((lane & 3) == 0) {
#pragma unroll
            for (int mt = 0; mt < 2; mt++)
#pragma unroll
                for (int h = 0; h < 2; h++)
                    atomicAdd(&rowsq[wm * 32 + mt * 16 + h * 8 + qrow], s2[mt][h]);
        }
        __syncthreads();
#pragma unroll
        for (int mt = 0; mt < 2; mt++)
#pragma unroll
            for (int h = 0; h < 2; h++) {
                int row = wm * 32 + mt * 16 + h * 8 + qrow;
                int g = row0 + row;
                if (g < NNODES) {
                    float inv = 1.0f / fmaxf(sqrtf(rowsq[row]), 1e-12f);
#pragma unroll
                    for (int nt = 0; nt < 8; nt++) {
                        int c0 = wn * 64 + nt * 8 + qcol;
                        float2 v = make_float2(acc[mt][nt][h * 2] * inv,
                                               acc[mt][nt][h * 2 + 1] * inv);
                        *(float2*)(op + (size_t)g * DHID + c0) = v;
                    }
                }
            }
    }
}

// ---------------------------------------------------------------------------
// Launch: CSR build (once, shared by both layers) -> prep -> gemm1 -> gemm2
// ---------------------------------------------------------------------------
extern "C" void kernel_launch(void* const* d_in, const int* in_sizes, int n_in,
                              void* d_out, int out_size) {
    const float* x      = (const float*)d_in[0];
    const float* W1     = (const float*)d_in[1];
    const float* loopW1 = (const float*)d_in[2];
    const float* b1     = (const float*)d_in[3];
    const float* W2     = (const float*)d_in[4];
    const float* loopW2 = (const float*)d_in[5];
    const float* b2     = (const float*)d_in[6];
    const int*   src    = (const int*)d_in[7];
    const int*   dst    = (const int*)d_in[8];
    const int*   et     = (const int*)d_in[9];
    float* out = (float*)d_out;

    cudaFuncSetAttribute(gemm_mma_kernel,
                         cudaFuncAttributeMaxDynamicSharedMemorySize, SMEM_BYTES);

    int eblocks = (EDGES + 255) / 256;          // 3125
    int gblocks = (NNODES + BM - 1) / BM;       // 391
    int pblocks = (2 * DHID * KTOT + 255) / 256;

    // CSR build
    zero_cnt_kernel<<<(NR / 4 + 255) / 256, 256>>>();
    hist_kernel<<<eblocks, 256>>>(dst, et);
    scan1_kernel<<<NBLK1, 256>>>();
    scan2_kernel<<<1, 512>>>();
    scan3_kernel<<<(NR + 255) / 256, 256>>>();
    fill_kernel<<<eblocks, 256>>>(src, dst, et);

    prep_B_kernel<<<pblocks, 256>>>(W1, loopW1, W2, loopW2);

    // Layer 1: relu( gather(x) @ W + x @ loopW + b1 ) -> g_h
    gemm_mma_kernel<<<gblocks, 256, SMEM_BYTES>>>(x, 0, 0, b1, nullptr, 1, 0);
    // Layer 2: normalize( gather(g_h) @ W + g_h @ loopW + b2 ) -> out
    gemm_mma_kernel<<<gblocks, 256, SMEM_BYTES>>>(nullptr, 1, 1, b2, out, 0, 1);
}